// round 6
// baseline (speedup 1.0000x reference)
#include <cuda_runtime.h>
#include <cuda_fp16.h>

// LaplacianReg: B=32, V=65536, K=8, C=3
// result[b,v,c] = (d[b,v,c] + sum_k w[v,k]*d[b,idx[v,k],c])^2,  d = out - tgt
//
// fp16 scratch [v][c][b] (96 halfs = 192B = 12 uint4 per v).
// Pass 2: 2 v per warp (24 active lanes x uint4 = 2 rows per LDG),
// fp32 accumulation (precision-safe), smem idx/weight broadcast.

#define BB 32
#define VV 65536
#define CC 3
#define KK 8
#define ROWH 96        // halfs per v
#define ROWQ 12        // uint4 per v
#define TILE_V 64
#define P1PAD 104      // pass-1 smem halfs per v row
#define P2PAD 100      // pass-2 smem floats per v row (conflict-free reads)

// 12.6 MB fp16 scratch, uint4 for 16B alignment
__device__ uint4 g_diff_raw[(size_t)VV * ROWQ];

// ---------------- Pass 1: diff + fp16 convert + transpose ----------------
__global__ void __launch_bounds__(256) diff_transpose_kernel(
    const float* __restrict__ out_, const float* __restrict__ tgt_)
{
    __shared__ __half s[TILE_V * P1PAD];

    const int tid = threadIdx.x;
    const int v0  = blockIdx.x * TILE_V;

#pragma unroll
    for (int it = 0; it < 6; it++) {
        int r4   = tid + it * 256;          // 0..1535
        int b    = r4 / 48;
        int off4 = r4 - b * 48;
        const float4* o4 = (const float4*)(out_ + (size_t)b * (VV * CC) + (size_t)v0 * CC);
        const float4* t4 = (const float4*)(tgt_ + (size_t)b * (VV * CC) + (size_t)v0 * CC);
        float4 o = o4[off4];
        float4 t = t4[off4];
        float d[4] = { o.x - t.x, o.y - t.y, o.z - t.z, o.w - t.w };
        int off = off4 * 4;                 // 0..191 = v_local*3 + c
#pragma unroll
        for (int j = 0; j < 4; j++) {
            int oo = off + j;
            int vl = oo / 3;
            int c  = oo - vl * 3;
            s[vl * P1PAD + c * 32 + b] = __float2half_rn(d[j]);
        }
    }
    __syncthreads();

    uint4* gout = g_diff_raw + (size_t)v0 * ROWQ;
#pragma unroll
    for (int it = 0; it < 3; it++) {
        int f    = tid + it * 256;          // 0..767
        int flat = f * 8;                   // half index in tile
        int vl   = flat / 96;
        int off  = flat - vl * 96;
        gout[f] = *(const uint4*)(s + vl * P1PAD + off);
    }
}

// ---------------- Pass 2: gather + fp32 accumulate + square ----------------
// block 256 = 8 warps; warp handles 2 v; block handles 16 v.
__global__ void __launch_bounds__(256) lap_kernel(
    const int* __restrict__ nidx, const float* __restrict__ nw,
    float* __restrict__ res)
{
    __shared__ float s[16 * P2PAD];
    __shared__ int   si[128];
    __shared__ float sw[128];

    const int tid = threadIdx.x;
    const int v0  = blockIdx.x * 16;

    if (tid < 128) {
        si[tid] = nidx[v0 * KK + tid];
    } else {
        sw[tid - 128] = nw[v0 * KK + (tid - 128)];
    }
    __syncthreads();

    const int lane = tid & 31;
    const int wrp  = tid >> 5;

    if (lane < 24) {
        const int g   = lane >= 12 ? 1 : 0;
        const int sub = lane - g * 12;
        const int vl  = wrp * 2 + g;        // 0..15
        const int v   = v0 + vl;

        const uint4* gd = g_diff_raw;

        // self row (weight 1) -> fp32 accumulators
        uint4 r = __ldg(gd + (size_t)v * ROWQ + sub);
        float2 p0 = __half22float2(*(__half2*)&r.x);
        float2 p1 = __half22float2(*(__half2*)&r.y);
        float2 p2 = __half22float2(*(__half2*)&r.z);
        float2 p3 = __half22float2(*(__half2*)&r.w);
        float a0 = p0.x, a1 = p0.y, a2 = p1.x, a3 = p1.y;
        float a4 = p2.x, a5 = p2.y, a6 = p3.x, a7 = p3.y;

        const int*   ip = si + vl * KK;
        const float* wp = sw + vl * KK;

#pragma unroll
        for (int k = 0; k < KK; k++) {
            int   nk = ip[k];
            float wk = wp[k];
            uint4 q  = __ldg(gd + (size_t)nk * ROWQ + sub);
            float2 q0 = __half22float2(*(__half2*)&q.x);
            float2 q1 = __half22float2(*(__half2*)&q.y);
            float2 q2 = __half22float2(*(__half2*)&q.z);
            float2 q3 = __half22float2(*(__half2*)&q.w);
            a0 = fmaf(wk, q0.x, a0);
            a1 = fmaf(wk, q0.y, a1);
            a2 = fmaf(wk, q1.x, a2);
            a3 = fmaf(wk, q1.y, a3);
            a4 = fmaf(wk, q2.x, a4);
            a5 = fmaf(wk, q2.y, a5);
            a6 = fmaf(wk, q3.x, a6);
            a7 = fmaf(wk, q3.y, a7);
        }

        float4 w1 = { a0 * a0, a1 * a1, a2 * a2, a3 * a3 };
        float4 w2 = { a4 * a4, a5 * a5, a6 * a6, a7 * a7 };
        // flat = c*32+b layout within row
        *(float4*)(s + vl * P2PAD + sub * 8)     = w1;
        *(float4*)(s + vl * P2PAD + sub * 8 + 4) = w2;
    }
    __syncthreads();

    // output (B,V,C): thread -> b = tid/8, vq = tid%8; two v per thread
    const int b  = tid >> 3;
    const int vq = tid & 7;
#pragma unroll
    for (int h = 0; h < 2; h++) {
        int vl = vq + h * 8;
        const float* sr = s + vl * P2PAD + b;
        float r0 = sr[0];
        float r1 = sr[32];
        float r2 = sr[64];
        float* op = res + (size_t)b * (VV * CC) + (size_t)(v0 + vl) * CC;
        op[0] = r0;
        op[1] = r1;
        op[2] = r2;
    }
}

extern "C" void kernel_launch(void* const* d_in, const int* in_sizes, int n_in,
                              void* d_out, int out_size)
{
    const float* out_ = (const float*)d_in[0];
    const float* tgt_ = (const float*)d_in[1];
    const int*   nidx = (const int*)  d_in[2];
    const float* nw   = (const float*)d_in[3];
    float*       res  = (float*)d_out;

    diff_transpose_kernel<<<VV / TILE_V, 256>>>(out_, tgt_);
    lap_kernel<<<VV / 16, 256>>>(nidx, nw, res);
}

// round 8
// speedup vs baseline: 1.0082x; 1.0082x over previous
#include <cuda_runtime.h>
#include <cuda_fp16.h>
#include <cstdint>

// LaplacianReg: B=32, V=65536, K=8, C=3
// result[b,v,c] = (d[b,v,c] + sum_k w[v,k]*d[b,idx[v,k],c])^2,  d = out - tgt
//
// fp16 scratch [v][c][b] (96 halfs = 192B = 12 uint4 per v).
// Pass 2: 2 v per warp; 8 neighbor-row gathers issued as cp.async.cg (16B/lane,
// no dest regs -> guaranteed MLP, low reg count, high occupancy), self row via
// LDG; fp32 accumulation; smem-staged transposed output.

#define BB 32
#define VV 65536
#define CC 3
#define KK 8
#define ROWH 96        // halfs per v
#define ROWQ 12        // uint4 per v
#define TILE_V 64
#define P1PAD 104      // pass-1 smem halfs per v row
#define P2PAD 100      // pass-2 smem floats per v row
#define SLOT 384       // stage bytes per k-slot (2 rows)

// 12.6 MB fp16 scratch, uint4 for 16B alignment
__device__ uint4 g_diff_raw[(size_t)VV * ROWQ];

// ---------------- Pass 1: diff + fp16 convert + transpose ----------------
__global__ void __launch_bounds__(256) diff_transpose_kernel(
    const float* __restrict__ out_, const float* __restrict__ tgt_)
{
    __shared__ __half s[TILE_V * P1PAD];

    const int tid = threadIdx.x;
    const int v0  = blockIdx.x * TILE_V;

#pragma unroll
    for (int it = 0; it < 6; it++) {
        int r4   = tid + it * 256;          // 0..1535
        int b    = r4 / 48;
        int off4 = r4 - b * 48;
        const float4* o4 = (const float4*)(out_ + (size_t)b * (VV * CC) + (size_t)v0 * CC);
        const float4* t4 = (const float4*)(tgt_ + (size_t)b * (VV * CC) + (size_t)v0 * CC);
        float4 o = o4[off4];
        float4 t = t4[off4];
        float d[4] = { o.x - t.x, o.y - t.y, o.z - t.z, o.w - t.w };
        int off = off4 * 4;                 // 0..191 = v_local*3 + c
#pragma unroll
        for (int j = 0; j < 4; j++) {
            int oo = off + j;
            int vl = oo / 3;
            int c  = oo - vl * 3;
            s[vl * P1PAD + c * 32 + b] = __float2half_rn(d[j]);
        }
    }
    __syncthreads();

    uint4* gout = g_diff_raw + (size_t)v0 * ROWQ;
#pragma unroll
    for (int it = 0; it < 3; it++) {
        int f    = tid + it * 256;          // 0..767
        int flat = f * 8;
        int vl   = flat / 96;
        int off  = flat - vl * 96;
        gout[f] = *(const uint4*)(s + vl * P1PAD + off);
    }
}

// ---------------- Pass 2: cp.async gather + fp32 accumulate + square -------
// block 256 = 8 warps; warp handles 2 v; block handles 16 v.
__global__ void __launch_bounds__(256) lap_kernel(
    const int* __restrict__ nidx, const float* __restrict__ nw,
    float* __restrict__ res)
{
    __shared__ __align__(16) char stage[8 * KK * SLOT];   // 24576 B
    __shared__ float s[16 * P2PAD];
    __shared__ int   si[128];
    __shared__ float sw[128];

    const int tid = threadIdx.x;
    const int v0  = blockIdx.x * 16;

    if (tid < 128) {
        si[tid] = nidx[v0 * KK + tid];
    } else {
        sw[tid - 128] = nw[v0 * KK + (tid - 128)];
    }
    __syncthreads();

    const int lane = tid & 31;
    const int wrp  = tid >> 5;

    if (lane < 24) {
        const int g   = lane >= 12 ? 1 : 0;
        const int sub = lane - g * 12;
        const int vl  = wrp * 2 + g;        // 0..15
        const int vw  = v0 + wrp * 2;       // first v of this warp

        // fire 8 neighbor-row copies, 16B per lane, no dest registers
        unsigned int sb = (unsigned int)__cvta_generic_to_shared(stage)
                          + wrp * (KK * SLOT) + lane * 16;
        const int* ip = si + vl * KK;
#pragma unroll
        for (int k = 0; k < KK; k++) {
            int nk = ip[k];
            const void* src = (const void*)(g_diff_raw + (size_t)nk * ROWQ + sub);
            unsigned int dst = sb + k * SLOT;
            asm volatile("cp.async.cg.shared.global [%0], [%1], 16;\n"
                         :: "r"(dst), "l"(src));
        }
        asm volatile("cp.async.commit_group;\n");

        // self rows (v, v+1 contiguous: 24 lanes x uint4 = 384B) via LDG
        uint4 r = __ldg(g_diff_raw + (size_t)vw * ROWQ + lane);
        float2 p0 = __half22float2(*(__half2*)&r.x);
        float2 p1 = __half22float2(*(__half2*)&r.y);
        float2 p2 = __half22float2(*(__half2*)&r.z);
        float2 p3 = __half22float2(*(__half2*)&r.w);
        float a0 = p0.x, a1 = p0.y, a2 = p1.x, a3 = p1.y;
        float a4 = p2.x, a5 = p2.y, a6 = p3.x, a7 = p3.y;

        asm volatile("cp.async.wait_group 0;\n");

        const float* wp = sw + vl * KK;
        const char*  rb = stage + wrp * (KK * SLOT) + lane * 16;
#pragma unroll
        for (int k = 0; k < KK; k++) {
            float wk = wp[k];
            uint4 q  = *(const uint4*)(rb + k * SLOT);
            float2 q0 = __half22float2(*(__half2*)&q.x);
            float2 q1 = __half22float2(*(__half2*)&q.y);
            float2 q2 = __half22float2(*(__half2*)&q.z);
            float2 q3 = __half22float2(*(__half2*)&q.w);
            a0 = fmaf(wk, q0.x, a0);
            a1 = fmaf(wk, q0.y, a1);
            a2 = fmaf(wk, q1.x, a2);
            a3 = fmaf(wk, q1.y, a3);
            a4 = fmaf(wk, q2.x, a4);
            a5 = fmaf(wk, q2.y, a5);
            a6 = fmaf(wk, q3.x, a6);
            a7 = fmaf(wk, q3.y, a7);
        }

        float4 w1 = { a0 * a0, a1 * a1, a2 * a2, a3 * a3 };
        float4 w2 = { a4 * a4, a5 * a5, a6 * a6, a7 * a7 };
        *(float4*)(s + vl * P2PAD + sub * 8)     = w1;
        *(float4*)(s + vl * P2PAD + sub * 8 + 4) = w2;
    }
    __syncthreads();

    // output (B,V,C): thread -> b = tid/8, vq = tid%8; two v per thread
    const int b  = tid >> 3;
    const int vq = tid & 7;
#pragma unroll
    for (int h = 0; h < 2; h++) {
        int vl = vq + h * 8;
        const float* sr = s + vl * P2PAD + b;
        float r0 = sr[0];
        float r1 = sr[32];
        float r2 = sr[64];
        float* op = res + (size_t)b * (VV * CC) + (size_t)(v0 + vl) * CC;
        op[0] = r0;
        op[1] = r1;
        op[2] = r2;
    }
}

extern "C" void kernel_launch(void* const* d_in, const int* in_sizes, int n_in,
                              void* d_out, int out_size)
{
    const float* out_ = (const float*)d_in[0];
    const float* tgt_ = (const float*)d_in[1];
    const int*   nidx = (const int*)  d_in[2];
    const float* nw   = (const float*)d_in[3];
    float*       res  = (float*)d_out;

    diff_transpose_kernel<<<VV / TILE_V, 256>>>(out_, tgt_);
    lap_kernel<<<VV / 16, 256>>>(nidx, nw, res);
}